// round 16
// baseline (speedup 1.0000x reference)
#include <cuda_runtime.h>
#include <cuda_fp16.h>

// HDBLUT 2x superresolution, GB300 sm_103a. Round 16:
//  PDL done right: pack kernel triggers launch_dependents right after its
//  g_pimg writes; main fills the 96KB smem LUT directly from msb_weight
//  (independent work, before the wait), THEN griddepcontrol.wait, then the
//  gather loop. R14 byte-offset core, 2 CTAs/SM x 512 threads.

#define NN 2048
#define NTILES (1024 * 64)        // row-pairs x 32-col tiles
#define THREADS 512
#define WARPS_PER_CTA (THREADS / 32)
#define LUT_E (3 * 4096)
#define PSTRIDE 260
#define PWORDS 257
#define SMEM_BYTES (LUT_E * 8)

__device__ unsigned g_pimg[NN * PSTRIDE];      // nibble-packed image

__device__ __forceinline__ int refl(int t) {
    t = (t < 0) ? -t : t;
    return (t >= NN) ? (2 * NN - 2 - t) : t;
}

__device__ __forceinline__ __half2 u2h(unsigned u) {
    return *reinterpret_cast<__half2*>(&u);
}

// One block per image row: int4 loads staged through smem, nibble-pack with
// reflection baked in. Triggers dependent launch after stores.
__global__ void hdblut_pack(const int* __restrict__ img)
{
    __shared__ int srow[2056];
    const int tid = threadIdx.x;
    const int r = blockIdx.x;

    const int4* row4 = reinterpret_cast<const int4*>(img + (size_t)r * NN);
    #pragma unroll
    for (int k = 0; k < 2; k++) {
        int i = tid + k * 256;
        int4 v = __ldg(row4 + i);
        srow[2 + i * 4 + 0] = v.x;
        srow[2 + i * 4 + 1] = v.y;
        srow[2 + i * 4 + 2] = v.z;
        srow[2 + i * 4 + 3] = v.w;
    }
    __syncthreads();
    if (tid == 0) {
        srow[0] = srow[4];
        srow[1] = srow[3];
        #pragma unroll
        for (int i = 0; i < 6; i++)
            srow[2050 + i] = srow[2048 - i];
    }
    __syncthreads();
    for (int wi = tid; wi < PWORDS; wi += 256) {
        const int* s = srow + wi * 8;
        unsigned val = 0;
        #pragma unroll
        for (int j = 0; j < 8; j++)
            val |= (unsigned)(s[j] & 15) << (4 * j);
        g_pimg[(size_t)r * PSTRIDE + wi] = val;
    }
#if __CUDA_ARCH__ >= 900
    asm volatile("griddepcontrol.launch_dependents;");
#endif
}

__global__ __launch_bounds__(THREADS, 2)
void hdblut_main(const float4* __restrict__ wlut, float2* __restrict__ out)
{
    extern __shared__ uint2 slut[];   // 96 KB fp16 LUT (1/3 folded)

    // Independent work FIRST: fill smem LUT straight from gmem fp32.
    // This overlaps the still-running pack kernel under PDL.
    for (int i = threadIdx.x; i < LUT_E; i += THREADS) {
        float4 v = __ldg(wlut + i);
        const float s = 1.0f / 3.0f;
        __half2 lo = __floats2half2_rn(v.x * s, v.y * s);
        __half2 hi = __floats2half2_rn(v.z * s, v.w * s);
        uint2 u;
        u.x = *reinterpret_cast<unsigned*>(&lo);
        u.y = *reinterpret_cast<unsigned*>(&hi);
        slut[i] = u;
    }

    // NOW wait for the pack kernel's g_pimg writes.
#if __CUDA_ARCH__ >= 900
    asm volatile("griddepcontrol.wait;");
#endif
    __syncthreads();

    const char* lutb = reinterpret_cast<const char*>(slut);
    const int warp = threadIdx.x >> 5;
    const int lane = threadIdx.x & 31;
    const int gwarp  = blockIdx.x * WARPS_PER_CTA + warp;
    const int nwarps = gridDim.x * WARPS_PER_CTA;

    for (int t = gwarp; t < NTILES; t += nwarps) {
        const int I  = (t >> 6) << 1;       // low-res row pair (I, I+1)
        const int Jb = (t & 63) << 5;

        // 6 packed rows I-2..I+3; nibble j of rc[i] = img col J-2+j (J=Jb+lane)
        unsigned rc[6];
        {
            const int pos = Jb + lane;
            const int wi  = pos >> 3;
            const int sh  = (pos & 7) * 4;
            #pragma unroll
            for (int i = 0; i < 6; i++) {
                const unsigned* pr = g_pimg + (size_t)refl(I - 2 + i) * PSTRIDE + wi;
                unsigned w0 = __ldg(pr);
                unsigned w1 = __ldg(pr + 1);
                rc[i] = __funnelshift_r(w0, w1, sh);
            }
        }

        float acc[2][4];
        #pragma unroll
        for (int ro = 0; ro < 2; ro++)
            acc[ro][0] = acc[ro][1] = acc[ro][2] = acc[ro][3] = 0.f;

        // Pre-scaled nibble extraction: value<<tt, one SHF + one LOP3.
        #define EX(v, jj, tt) \
            (((4*(jj) >= (tt)) ? ((v) >> (4*(jj) - (tt)))               \
                               : ((v) << ((tt) - 4*(jj)))) & (15u << (tt)))

        #define GOFF(ro, k, bx, by, cx, cy)                              \
            (a11 + (unsigned)((k) * 32768) +                             \
             EX(rc[2 + (ro) + (bx)], 2 + (by), 7) +                      \
             EX(rc[2 + (ro) + (cx)], 2 + (cy), 3))

        #define ROT3(ro, b0x,b0y,c0x,c0y, b1x,b1y,c1x,c1y, b2x,b2y,c2x,c2y, \
                     i00,i01,i10,i11) do {                                  \
            uint2 h0 = *reinterpret_cast<const uint2*>(                     \
                           lutb + GOFF(ro, 0, b0x,b0y, c0x,c0y));           \
            uint2 h1 = *reinterpret_cast<const uint2*>(                     \
                           lutb + GOFF(ro, 1, b1x,b1y, c1x,c1y));           \
            uint2 h2 = *reinterpret_cast<const uint2*>(                     \
                           lutb + GOFF(ro, 2, b2x,b2y, c2x,c2y));           \
            __half2 sA = __hadd2(__hadd2(u2h(h0.x), u2h(h1.x)), u2h(h2.x)); \
            __half2 sB = __hadd2(__hadd2(u2h(h0.y), u2h(h1.y)), u2h(h2.y)); \
            float2 fA = __half22float2(sA);                                 \
            float2 fB = __half22float2(sB);                                 \
            float fv[4] = {fA.x, fA.y, fB.x, fB.y};                         \
            acc[ro][0] += fv[i00]; acc[ro][1] += fv[i01];                   \
            acc[ro][2] += fv[i10]; acc[ro][3] += fv[i11];                   \
        } while (0)

        #pragma unroll
        for (int ro = 0; ro < 2; ro++) {
            const unsigned a11 = (rc[2 + ro] << 3) & (15u << 11);
            // r = 0: offsets as-is       perm (0,1,2,3)
            ROT3(ro,  0, 1,  0, 2,   1, 1,  2, 2,   1, 2,  2, 1,  0,1,2,3);
            // r = 1: (x,y)->(y,-x)       perm (2,0,3,1)
            ROT3(ro,  1, 0,  2, 0,   1,-1,  2,-2,   2,-1,  1,-2,  2,0,3,1);
            // r = 2: (x,y)->(-x,-y)      perm (3,2,1,0)
            ROT3(ro,  0,-1,  0,-2,  -1,-1, -2,-2,  -1,-2, -2,-1,  3,2,1,0);
            // r = 3: (x,y)->(-y,x)       perm (1,3,0,2)
            ROT3(ro, -1, 0, -2, 0,  -1, 1, -2, 2,  -2, 1, -1, 2,  1,3,0,2);
        }

        #undef ROT3
        #undef GOFF
        #undef EX

        const int J = Jb + lane;
        const size_t base = (size_t)(2 * I) * 2048 + J;
        out[base        ] = make_float2(acc[0][0], acc[0][1]);
        out[base + 2048 ] = make_float2(acc[0][2], acc[0][3]);
        out[base + 4096 ] = make_float2(acc[1][0], acc[1][1]);
        out[base + 6144 ] = make_float2(acc[1][2], acc[1][3]);
    }
}

extern "C" void kernel_launch(void* const* d_in, const int* in_sizes, int n_in,
                              void* d_out, int out_size)
{
    const int*    img  = (const int*)d_in[0];
    const float4* wlut = (const float4*)d_in[1];
    float2*       out  = (float2*)d_out;

    int sms = 0;
    cudaDeviceGetAttribute(&sms, cudaDevAttrMultiProcessorCount, 0);
    if (sms <= 0) sms = 148;

    hdblut_pack<<<NN, 256>>>(img);

    cudaFuncSetAttribute(hdblut_main,
                         cudaFuncAttributeMaxDynamicSharedMemorySize, SMEM_BYTES);

    cudaLaunchConfig_t cfg = {};
    cfg.gridDim  = dim3(2 * sms, 1, 1);
    cfg.blockDim = dim3(THREADS, 1, 1);
    cfg.dynamicSmemBytes = SMEM_BYTES;
    cfg.stream = 0;
    cudaLaunchAttribute attrs[1];
    attrs[0].id = cudaLaunchAttributeProgrammaticStreamSerialization;
    attrs[0].val.programmaticStreamSerializationAllowed = 1;
    cfg.attrs = attrs;
    cfg.numAttrs = 1;
    cudaLaunchKernelEx(&cfg, hdblut_main, wlut, out);
}

// round 17
// speedup vs baseline: 1.0146x; 1.0146x over previous
#include <cuda_runtime.h>
#include <cuda_fp16.h>

// HDBLUT 2x superresolution, GB300 sm_103a. Round 17 (final config):
//  = Round 14 (best measured, 50.88us) + streaming output stores.
//  - prelude: image nibble-pack (row/block, int4 via smem)
//  - main: 96KB fp16 smem LUT filled straight from msb_weight (1/3 folded),
//    PDL launch, R12 byte-offset gather core, 2 CTAs/SM x 512 threads.
//  Main loop is at its LDS-conflict floor (~46.5us): 24 random LDS.64
//  gathers/warp-iter x ~6.4 conflict-wavefronts == measured L1 ~80-84%.

#define NN 2048
#define NTILES (1024 * 64)        // row-pairs x 32-col tiles
#define THREADS 512
#define WARPS_PER_CTA (THREADS / 32)
#define LUT_E (3 * 4096)
#define PSTRIDE 260
#define PWORDS 257
#define SMEM_BYTES (LUT_E * 8)

__device__ unsigned g_pimg[NN * PSTRIDE];      // nibble-packed image

__device__ __forceinline__ int refl(int t) {
    t = (t < 0) ? -t : t;
    return (t >= NN) ? (2 * NN - 2 - t) : t;
}

__device__ __forceinline__ __half2 u2h(unsigned u) {
    return *reinterpret_cast<__half2*>(&u);
}

// One block per image row: int4 loads staged through smem, nibble-pack with
// reflection baked in.
__global__ void hdblut_pack(const int* __restrict__ img)
{
    __shared__ int srow[2056];
    const int tid = threadIdx.x;
    const int r = blockIdx.x;

    const int4* row4 = reinterpret_cast<const int4*>(img + (size_t)r * NN);
    #pragma unroll
    for (int k = 0; k < 2; k++) {
        int i = tid + k * 256;
        int4 v = __ldg(row4 + i);
        srow[2 + i * 4 + 0] = v.x;
        srow[2 + i * 4 + 1] = v.y;
        srow[2 + i * 4 + 2] = v.z;
        srow[2 + i * 4 + 3] = v.w;
    }
    __syncthreads();
    if (tid == 0) {
        srow[0] = srow[4];
        srow[1] = srow[3];
        #pragma unroll
        for (int i = 0; i < 6; i++)
            srow[2050 + i] = srow[2048 - i];
    }
    __syncthreads();
    for (int wi = tid; wi < PWORDS; wi += 256) {
        const int* s = srow + wi * 8;
        unsigned val = 0;
        #pragma unroll
        for (int j = 0; j < 8; j++)
            val |= (unsigned)(s[j] & 15) << (4 * j);
        g_pimg[(size_t)r * PSTRIDE + wi] = val;
    }
#if __CUDA_ARCH__ >= 900
    asm volatile("griddepcontrol.launch_dependents;");
#endif
}

__global__ __launch_bounds__(THREADS, 2)
void hdblut_main(const float4* __restrict__ wlut, float2* __restrict__ out)
{
    extern __shared__ uint2 slut[];   // 96 KB fp16 LUT (1/3 folded)

    // Independent of the pack kernel: fill smem LUT straight from fp32.
    for (int i = threadIdx.x; i < LUT_E; i += THREADS) {
        float4 v = __ldg(wlut + i);
        const float s = 1.0f / 3.0f;
        __half2 lo = __floats2half2_rn(v.x * s, v.y * s);
        __half2 hi = __floats2half2_rn(v.z * s, v.w * s);
        uint2 u;
        u.x = *reinterpret_cast<unsigned*>(&lo);
        u.y = *reinterpret_cast<unsigned*>(&hi);
        slut[i] = u;
    }

#if __CUDA_ARCH__ >= 900
    asm volatile("griddepcontrol.wait;");
#endif
    __syncthreads();

    const char* lutb = reinterpret_cast<const char*>(slut);
    const int warp = threadIdx.x >> 5;
    const int lane = threadIdx.x & 31;
    const int gwarp  = blockIdx.x * WARPS_PER_CTA + warp;
    const int nwarps = gridDim.x * WARPS_PER_CTA;

    for (int t = gwarp; t < NTILES; t += nwarps) {
        const int I  = (t >> 6) << 1;       // low-res row pair (I, I+1)
        const int Jb = (t & 63) << 5;

        // 6 packed rows I-2..I+3; nibble j of rc[i] = img col J-2+j (J=Jb+lane)
        unsigned rc[6];
        {
            const int pos = Jb + lane;
            const int wi  = pos >> 3;
            const int sh  = (pos & 7) * 4;
            #pragma unroll
            for (int i = 0; i < 6; i++) {
                const unsigned* pr = g_pimg + (size_t)refl(I - 2 + i) * PSTRIDE + wi;
                unsigned w0 = __ldg(pr);
                unsigned w1 = __ldg(pr + 1);
                rc[i] = __funnelshift_r(w0, w1, sh);
            }
        }

        float acc[2][4];
        #pragma unroll
        for (int ro = 0; ro < 2; ro++)
            acc[ro][0] = acc[ro][1] = acc[ro][2] = acc[ro][3] = 0.f;

        // Pre-scaled nibble extraction: value<<tt, one SHF + one LOP3.
        #define EX(v, jj, tt) \
            (((4*(jj) >= (tt)) ? ((v) >> (4*(jj) - (tt)))               \
                               : ((v) << ((tt) - 4*(jj)))) & (15u << (tt)))

        #define GOFF(ro, k, bx, by, cx, cy)                              \
            (a11 + (unsigned)((k) * 32768) +                             \
             EX(rc[2 + (ro) + (bx)], 2 + (by), 7) +                      \
             EX(rc[2 + (ro) + (cx)], 2 + (cy), 3))

        #define ROT3(ro, b0x,b0y,c0x,c0y, b1x,b1y,c1x,c1y, b2x,b2y,c2x,c2y, \
                     i00,i01,i10,i11) do {                                  \
            uint2 h0 = *reinterpret_cast<const uint2*>(                     \
                           lutb + GOFF(ro, 0, b0x,b0y, c0x,c0y));           \
            uint2 h1 = *reinterpret_cast<const uint2*>(                     \
                           lutb + GOFF(ro, 1, b1x,b1y, c1x,c1y));           \
            uint2 h2 = *reinterpret_cast<const uint2*>(                     \
                           lutb + GOFF(ro, 2, b2x,b2y, c2x,c2y));           \
            __half2 sA = __hadd2(__hadd2(u2h(h0.x), u2h(h1.x)), u2h(h2.x)); \
            __half2 sB = __hadd2(__hadd2(u2h(h0.y), u2h(h1.y)), u2h(h2.y)); \
            float2 fA = __half22float2(sA);                                 \
            float2 fB = __half22float2(sB);                                 \
            float fv[4] = {fA.x, fA.y, fB.x, fB.y};                         \
            acc[ro][0] += fv[i00]; acc[ro][1] += fv[i01];                   \
            acc[ro][2] += fv[i10]; acc[ro][3] += fv[i11];                   \
        } while (0)

        #pragma unroll
        for (int ro = 0; ro < 2; ro++) {
            const unsigned a11 = (rc[2 + ro] << 3) & (15u << 11);
            // r = 0: offsets as-is       perm (0,1,2,3)
            ROT3(ro,  0, 1,  0, 2,   1, 1,  2, 2,   1, 2,  2, 1,  0,1,2,3);
            // r = 1: (x,y)->(y,-x)       perm (2,0,3,1)
            ROT3(ro,  1, 0,  2, 0,   1,-1,  2,-2,   2,-1,  1,-2,  2,0,3,1);
            // r = 2: (x,y)->(-x,-y)      perm (3,2,1,0)
            ROT3(ro,  0,-1,  0,-2,  -1,-1, -2,-2,  -1,-2, -2,-1,  3,2,1,0);
            // r = 3: (x,y)->(-y,x)       perm (1,3,0,2)
            ROT3(ro, -1, 0, -2, 0,  -1, 1, -2, 2,  -2, 1, -1, 2,  1,3,0,2);
        }

        #undef ROT3
        #undef GOFF
        #undef EX

        const int J = Jb + lane;
        const size_t base = (size_t)(2 * I) * 2048 + J;
        // Streaming stores: output is write-once, keep it out of L2's way.
        __stcs(out + base,        make_float2(acc[0][0], acc[0][1]));
        __stcs(out + base + 2048, make_float2(acc[0][2], acc[0][3]));
        __stcs(out + base + 4096, make_float2(acc[1][0], acc[1][1]));
        __stcs(out + base + 6144, make_float2(acc[1][2], acc[1][3]));
    }
}

extern "C" void kernel_launch(void* const* d_in, const int* in_sizes, int n_in,
                              void* d_out, int out_size)
{
    const int*    img  = (const int*)d_in[0];
    const float4* wlut = (const float4*)d_in[1];
    float2*       out  = (float2*)d_out;

    int sms = 0;
    cudaDeviceGetAttribute(&sms, cudaDevAttrMultiProcessorCount, 0);
    if (sms <= 0) sms = 148;

    hdblut_pack<<<NN, 256>>>(img);

    cudaFuncSetAttribute(hdblut_main,
                         cudaFuncAttributeMaxDynamicSharedMemorySize, SMEM_BYTES);

    cudaLaunchConfig_t cfg = {};
    cfg.gridDim  = dim3(2 * sms, 1, 1);
    cfg.blockDim = dim3(THREADS, 1, 1);
    cfg.dynamicSmemBytes = SMEM_BYTES;
    cfg.stream = 0;
    cudaLaunchAttribute attrs[1];
    attrs[0].id = cudaLaunchAttributeProgrammaticStreamSerialization;
    attrs[0].val.programmaticStreamSerializationAllowed = 1;
    cfg.attrs = attrs;
    cfg.numAttrs = 1;
    cudaLaunchKernelEx(&cfg, hdblut_main, wlut, out);
}